// round 1
// baseline (speedup 1.0000x reference)
#include <cuda_runtime.h>
#include <math.h>

constexpr int B_ = 8, T_ = 2048, E_ = 1024, D_ = 64;
constexpr int BT_ = B_ * T_;

// Scratch for Q, K, V projections (4 MB each). Static device arrays: no allocs.
__device__ float g_q[BT_ * D_];
__device__ float g_k[BT_ * D_];
__device__ float g_v[BT_ * D_];

// ---------------------------------------------------------------------------
// QKV projection: C[16384, 64] = x[16384, 1024] @ W[1024, 64] + b
// BM=64, BN=64, BK=16, 256 threads, each thread computes 4x4 outputs.
// blockIdx.y in {0,1,2} selects q/k/v.
// ---------------------------------------------------------------------------
__global__ __launch_bounds__(256) void qkv_proj_kernel(
    const float* __restrict__ x,
    const float* __restrict__ Wq, const float* __restrict__ bq,
    const float* __restrict__ Wk, const float* __restrict__ bk,
    const float* __restrict__ Wv, const float* __restrict__ bv)
{
    __shared__ float xs[64][17];   // [BM][BK+1]
    __shared__ float ws[16][65];   // [BK][BN+1]

    const float* W; const float* bias; float* out;
    if (blockIdx.y == 0)      { W = Wq; bias = bq; out = g_q; }
    else if (blockIdx.y == 1) { W = Wk; bias = bk; out = g_k; }
    else                      { W = Wv; bias = bv; out = g_v; }

    const int tid = threadIdx.x;
    const int tx = tid & 15, ty = tid >> 4;
    const int m0 = blockIdx.x * 64;

    float acc[4][4] = {};

    for (int k0 = 0; k0 < E_; k0 += 16) {
        #pragma unroll
        for (int it = 0; it < 4; it++) {
            int lin = tid + it * 256;                 // 0..1023
            int r = lin >> 4, c = lin & 15;
            xs[r][c] = x[(m0 + r) * E_ + k0 + c];
        }
        #pragma unroll
        for (int it = 0; it < 4; it++) {
            int lin = tid + it * 256;
            int r = lin >> 6, c = lin & 63;
            ws[r][c] = W[(k0 + r) * D_ + c];
        }
        __syncthreads();
        #pragma unroll
        for (int kk = 0; kk < 16; kk++) {
            float a[4], b[4];
            #pragma unroll
            for (int i = 0; i < 4; i++) a[i] = xs[ty * 4 + i][kk];
            #pragma unroll
            for (int j = 0; j < 4; j++) b[j] = ws[kk][tx * 4 + j];
            #pragma unroll
            for (int i = 0; i < 4; i++)
                #pragma unroll
                for (int j = 0; j < 4; j++)
                    acc[i][j] = fmaf(a[i], b[j], acc[i][j]);
        }
        __syncthreads();
    }

    #pragma unroll
    for (int i = 0; i < 4; i++) {
        int r = m0 + ty * 4 + i;
        #pragma unroll
        for (int j = 0; j < 4; j++) {
            int c = tx * 4 + j;
            out[r * D_ + c] = acc[i][j] + bias[c];
        }
    }
}

// ---------------------------------------------------------------------------
// Flash attention, fp32, online softmax.
// Block = (batch, 64-query tile), 256 threads (16x16), 4x4 register tiles.
// smem: Qs (plain), Ks (K^T with float4 XOR swizzle; reused as P plain),
//       Vs (plain). Exactly 48 KB static.
// ---------------------------------------------------------------------------
__global__ __launch_bounds__(256) void flash_attn_kernel(float* __restrict__ out)
{
    __shared__ float Qs[64 * 64];
    __shared__ float Ks[64 * 64];   // holds K (swizzled), later P (plain)
    __shared__ float Vs[64 * 64];

    float4* Qs4 = reinterpret_cast<float4*>(Qs);
    float4* Ks4 = reinterpret_cast<float4*>(Ks);
    float4* Vs4 = reinterpret_cast<float4*>(Vs);

    const int tid = threadIdx.x;
    const int tx = tid & 15, ty = tid >> 4;
    const int b  = blockIdx.y;
    const int m0 = blockIdx.x * 64;
    const float scale = 0.125f;  // 1/sqrt(64)

    const float* q = g_q + b * T_ * D_;
    const float* k = g_k + b * T_ * D_;
    const float* v = g_v + b * T_ * D_;
    const float4* q4 = reinterpret_cast<const float4*>(q);
    const float4* k4 = reinterpret_cast<const float4*>(k);
    const float4* v4 = reinterpret_cast<const float4*>(v);

    // Load Q tile [64 rows][16 float4 groups], plain layout.
    #pragma unroll
    for (int it = 0; it < 4; it++) {
        int lin = tid + it * 256;                 // row = lin>>4, cg = lin&15
        Qs4[lin] = q4[(m0 + (lin >> 4)) * 16 + (lin & 15)];
    }

    float o[4][4] = {};
    float mrow[4], lrow[4];
    #pragma unroll
    for (int i = 0; i < 4; i++) { mrow[i] = -INFINITY; lrow[i] = 0.0f; }

    const int ksw = tx & 7;          // read-side K swizzle ((row>>2)&7 with row=tx*4+j)
    const int ntiles = blockIdx.x + 1;

    for (int nt = 0; nt < ntiles; nt++) {
        const int n0 = nt * 64;
        __syncthreads();   // previous iteration's P/V consumers are done

        // Load K^T (swizzled) and V (plain), float4 granularity.
        #pragma unroll
        for (int it = 0; it < 4; it++) {
            int lin = tid + it * 256;
            int key = lin >> 4;
            int cg  = lin & 15;
            float4 kk = k4[(n0 + key) * 16 + cg];
            float4 vv = v4[(n0 + key) * 16 + cg];
            Ks4[key * 16 + (cg ^ ((key >> 2) & 7))] = kk;   // swizzled store
            Vs4[key * 16 + cg] = vv;
        }
        __syncthreads();

        // S = Q K^T  (each thread: rows ty*4+i, key-cols tx*4+j)
        float s[4][4] = {};
        #pragma unroll
        for (int dg = 0; dg < 16; dg++) {
            float4 qv[4], kv[4];
            #pragma unroll
            for (int i = 0; i < 4; i++) qv[i] = Qs4[(ty * 4 + i) * 16 + dg];
            #pragma unroll
            for (int j = 0; j < 4; j++) kv[j] = Ks4[(tx * 4 + j) * 16 + (dg ^ ksw)];
            #pragma unroll
            for (int i = 0; i < 4; i++)
                #pragma unroll
                for (int j = 0; j < 4; j++) {
                    s[i][j] = fmaf(qv[i].x, kv[j].x, s[i][j]);
                    s[i][j] = fmaf(qv[i].y, kv[j].y, s[i][j]);
                    s[i][j] = fmaf(qv[i].z, kv[j].z, s[i][j]);
                    s[i][j] = fmaf(qv[i].w, kv[j].w, s[i][j]);
                }
        }

        // Scale + causal mask.
        #pragma unroll
        for (int i = 0; i < 4; i++) {
            int qrow = m0 + ty * 4 + i;
            #pragma unroll
            for (int j = 0; j < 4; j++) {
                int kcol = n0 + tx * 4 + j;
                s[i][j] = (kcol <= qrow) ? s[i][j] * scale : -INFINITY;
            }
        }

        // Online softmax. Row group = 16 lanes sharing ty (lanes (ty&1)*16 + tx).
        #pragma unroll
        for (int i = 0; i < 4; i++) {
            float mx = fmaxf(fmaxf(s[i][0], s[i][1]), fmaxf(s[i][2], s[i][3]));
            #pragma unroll
            for (int sft = 8; sft >= 1; sft >>= 1)
                mx = fmaxf(mx, __shfl_xor_sync(0xffffffffu, mx, sft));
            float mnew = fmaxf(mrow[i], mx);
            float alpha = __expf(mrow[i] - mnew);
            float rs = 0.0f;
            #pragma unroll
            for (int j = 0; j < 4; j++) {
                s[i][j] = __expf(s[i][j] - mnew);
                rs += s[i][j];
            }
            #pragma unroll
            for (int sft = 8; sft >= 1; sft >>= 1)
                rs += __shfl_xor_sync(0xffffffffu, rs, sft);
            lrow[i] = lrow[i] * alpha + rs;
            mrow[i] = mnew;
            #pragma unroll
            for (int j = 0; j < 4; j++) o[i][j] *= alpha;
        }

        __syncthreads();   // everyone done reading K^T from Ks
        // Write P (plain layout) into the K buffer.
        #pragma unroll
        for (int i = 0; i < 4; i++)
            Ks4[(ty * 4 + i) * 16 + tx] = make_float4(s[i][0], s[i][1], s[i][2], s[i][3]);
        __syncthreads();

        // O += P V   (rows ty*4+i, dim-cols tx*4+j)
        #pragma unroll
        for (int kk = 0; kk < 64; kk++) {
            float pa[4];
            #pragma unroll
            for (int i = 0; i < 4; i++) pa[i] = Ks[(ty * 4 + i) * 64 + kk];
            float4 vb = Vs4[kk * 16 + tx];
            #pragma unroll
            for (int i = 0; i < 4; i++) {
                o[i][0] = fmaf(pa[i], vb.x, o[i][0]);
                o[i][1] = fmaf(pa[i], vb.y, o[i][1]);
                o[i][2] = fmaf(pa[i], vb.z, o[i][2]);
                o[i][3] = fmaf(pa[i], vb.w, o[i][3]);
            }
        }
    }

    // Epilogue: normalize and store.
    float4* out4 = reinterpret_cast<float4*>(out) + b * T_ * 16;
    #pragma unroll
    for (int i = 0; i < 4; i++) {
        float inv = 1.0f / lrow[i];
        int r = m0 + ty * 4 + i;
        out4[r * 16 + tx] = make_float4(o[i][0] * inv, o[i][1] * inv,
                                        o[i][2] * inv, o[i][3] * inv);
    }
}

// ---------------------------------------------------------------------------
extern "C" void kernel_launch(void* const* d_in, const int* in_sizes, int n_in,
                              void* d_out, int out_size)
{
    const float* x  = (const float*)d_in[0];
    const float* Wq = (const float*)d_in[1];
    const float* bq = (const float*)d_in[2];
    const float* Wk = (const float*)d_in[3];
    const float* bk = (const float*)d_in[4];
    const float* Wv = (const float*)d_in[5];
    const float* bv = (const float*)d_in[6];
    float* out = (float*)d_out;

    dim3 gproj(BT_ / 64, 3);
    qkv_proj_kernel<<<gproj, 256>>>(x, Wq, bq, Wk, bk, Wv, bv);

    dim3 gattn(T_ / 64, B_);
    flash_attn_kernel<<<gattn, 256>>>(out);
}

// round 4
// speedup vs baseline: 3.2379x; 3.2379x over previous
#include <cuda_runtime.h>
#include <cuda_fp16.h>
#include <math.h>
#include <stdint.h>

constexpr int B_ = 8, T_ = 2048, E_ = 1024, D_ = 64;
constexpr int BT_ = B_ * T_;
constexpr int NC_ = 192;   // concatenated q|k|v columns

// Split-fp16 representations of Q,K,V (from projection) and W (prepacked).
__device__ __half g_hi[BT_ * NC_];
__device__ __half g_lo[BT_ * NC_];
__device__ __half g_whi[E_ * NC_];
__device__ __half g_wlo[E_ * NC_];

// ---------------------------------------------------------------------------
// Helpers
// ---------------------------------------------------------------------------
__device__ __forceinline__ uint32_t su32(const void* p) {
    return (uint32_t)__cvta_generic_to_shared(p);
}
__device__ __forceinline__ void ldsm_x4(uint32_t* r, uint32_t a) {
    asm volatile("ldmatrix.sync.aligned.m8n8.x4.shared.b16 {%0,%1,%2,%3}, [%4];"
                 : "=r"(r[0]), "=r"(r[1]), "=r"(r[2]), "=r"(r[3]) : "r"(a));
}
__device__ __forceinline__ void ldsm_x4t(uint32_t* r, uint32_t a) {
    asm volatile("ldmatrix.sync.aligned.m8n8.x4.trans.shared.b16 {%0,%1,%2,%3}, [%4];"
                 : "=r"(r[0]), "=r"(r[1]), "=r"(r[2]), "=r"(r[3]) : "r"(a));
}
__device__ __forceinline__ void mma16816(float* c, const uint32_t* a, const uint32_t* b) {
    asm volatile("mma.sync.aligned.m16n8k16.row.col.f32.f16.f16.f32 "
                 "{%0,%1,%2,%3},{%4,%5,%6,%7},{%8,%9},{%0,%1,%2,%3};"
                 : "+f"(c[0]), "+f"(c[1]), "+f"(c[2]), "+f"(c[3])
                 : "r"(a[0]), "r"(a[1]), "r"(a[2]), "r"(a[3]), "r"(b[0]), "r"(b[1]));
}
// Split two floats into packed half2 (hi) and half2 (residual lo).
__device__ __forceinline__ void split2(float a, float b, uint32_t& hi, uint32_t& lo) {
    __half ha = __float2half_rn(a), hb = __float2half_rn(b);
    __half2 H = __halves2half2(ha, hb);
    hi = *reinterpret_cast<uint32_t*>(&H);
    __half2 L = __halves2half2(__float2half_rn(a - __half2float(ha)),
                               __float2half_rn(b - __half2float(hb)));
    lo = *reinterpret_cast<uint32_t*>(&L);
}

// ---------------------------------------------------------------------------
// W prepack: [1024 x 192] split halves.
// ---------------------------------------------------------------------------
__global__ void wprep_kernel(const float* __restrict__ Wq,
                             const float* __restrict__ Wk,
                             const float* __restrict__ Wv) {
    int idx = blockIdx.x * 256 + threadIdx.x;
    if (idx >= E_ * NC_) return;
    int k = idx / NC_, c = idx % NC_;
    float w = (c < 64) ? Wq[k * 64 + c] : (c < 128) ? Wk[k * 64 + c - 64]
                                                    : Wv[k * 64 + c - 128];
    __half h = __float2half_rn(w);
    g_whi[idx] = h;
    g_wlo[idx] = __float2half_rn(w - __half2float(h));
}

// ---------------------------------------------------------------------------
// Fused QKV projection: [16384,192] = x[16384,1024] @ W[1024,192] + bias.
// BM=64, BN=192, BK=32, 8 warps (4m x 2n), warp tile 16x96.
// Split-fp16: acc += Ahi*Bhi + Ahi*Blo + Alo*Bhi.
// Epilogue writes split halves for the attention kernel.
// ---------------------------------------------------------------------------
constexpr int XS_ = 40;   // xs row stride (halves): conflict-free for ldmatrix
constexpr int WS_ = 200;  // ws row stride

__global__ __launch_bounds__(256) void qkv_proj_kernel(
    const float* __restrict__ x,
    const float* __restrict__ bq, const float* __restrict__ bk,
    const float* __restrict__ bv)
{
    __shared__ __half xs[2][64 * XS_];
    __shared__ __half ws[2][32 * WS_];

    const int tid = threadIdx.x, wid = tid >> 5, lane = tid & 31;
    const int gid = lane >> 2, tig = lane & 3;
    const int m0 = blockIdx.x * 64;
    const int wm = (wid >> 1) * 16, wn = (wid & 1) * 96;

    float acc[12][4];
    #pragma unroll
    for (int j = 0; j < 12; j++)
        #pragma unroll
        for (int c = 0; c < 4; c++) acc[j][c] = 0.0f;

    for (int k0 = 0; k0 < E_; k0 += 32) {
        // Load & split x tile: 64x32 f32 -> 512 float4.
        #pragma unroll
        for (int i = 0; i < 2; i++) {
            int l2 = tid + i * 256;
            int r = l2 >> 3, cg = l2 & 7;
            float4 v = *(const float4*)&x[(size_t)(m0 + r) * E_ + k0 + cg * 4];
            uint32_t h0, l0, h1, l1;
            split2(v.x, v.y, h0, l0);
            split2(v.z, v.w, h1, l1);
            *(uint32_t*)&xs[0][r * XS_ + cg * 4]     = h0;
            *(uint32_t*)&xs[0][r * XS_ + cg * 4 + 2] = h1;
            *(uint32_t*)&xs[1][r * XS_ + cg * 4]     = l0;
            *(uint32_t*)&xs[1][r * XS_ + cg * 4 + 2] = l1;
        }
        // Load W tile halves: 32x192 -> 768 uint4 per buffer.
        #pragma unroll
        for (int i = 0; i < 3; i++) {
            int l2 = tid + i * 256;
            int r = l2 / 24, cg = l2 % 24;
            *(uint4*)&ws[0][r * WS_ + cg * 8] =
                *(const uint4*)&g_whi[(size_t)(k0 + r) * NC_ + cg * 8];
            *(uint4*)&ws[1][r * WS_ + cg * 8] =
                *(const uint4*)&g_wlo[(size_t)(k0 + r) * NC_ + cg * 8];
        }
        __syncthreads();

        #pragma unroll
        for (int kc = 0; kc < 2; kc++) {
            uint32_t ah[4], al[4];
            int arow = wm + (lane & 15);
            int acol = kc * 16 + (lane >> 4) * 8;
            ldsm_x4(ah, su32(&xs[0][arow * XS_ + acol]));
            ldsm_x4(al, su32(&xs[1][arow * XS_ + acol]));
            #pragma unroll
            for (int j = 0; j < 12; j += 2) {
                uint32_t bh[4], bl[4];
                int brow = kc * 16 + (lane & 15);
                int bcol = wn + 8 * j + (lane >> 4) * 8;
                ldsm_x4t(bh, su32(&ws[0][brow * WS_ + bcol]));
                ldsm_x4t(bl, su32(&ws[1][brow * WS_ + bcol]));
                mma16816(acc[j],     ah, bh);
                mma16816(acc[j],     ah, bl);
                mma16816(acc[j],     al, bh);
                mma16816(acc[j + 1], ah, bh + 2);
                mma16816(acc[j + 1], ah, bl + 2);
                mma16816(acc[j + 1], al, bh + 2);
            }
        }
        __syncthreads();
    }

    // Epilogue: add bias, split to halves, store.
    const int r0 = m0 + wm + gid;
    #pragma unroll
    for (int j = 0; j < 12; j++) {
        int col = wn + 8 * j + 2 * tig;
        const float* bias = (col < 64) ? bq : (col < 128) ? bk : bv;
        int bc = col & 63;
        float b0 = bias[bc], b1 = bias[bc + 1];
        uint32_t hi, lo;
        split2(acc[j][0] + b0, acc[j][1] + b1, hi, lo);
        *(uint32_t*)&g_hi[(size_t)r0 * NC_ + col] = hi;
        *(uint32_t*)&g_lo[(size_t)r0 * NC_ + col] = lo;
        split2(acc[j][2] + b0, acc[j][3] + b1, hi, lo);
        *(uint32_t*)&g_hi[(size_t)(r0 + 8) * NC_ + col] = hi;
        *(uint32_t*)&g_lo[(size_t)(r0 + 8) * NC_ + col] = lo;
    }
}

// ---------------------------------------------------------------------------
// Flash attention on HMMA. Br=64, Bc=64, 4 warps (16 query rows each).
// Q frags register-resident; S accumulator frags reinterpreted as P A-frags.
// ---------------------------------------------------------------------------
constexpr int KS_ = 72;  // smem row stride (halves), conflict-free

__global__ __launch_bounds__(128) void flash_attn_kernel(float* __restrict__ out)
{
    __shared__ __half Ks[2][64 * KS_];
    __shared__ __half Vs[2][64 * KS_];

    const int tid = threadIdx.x, wid = tid >> 5, lane = tid & 31;
    const int gid = lane >> 2, tig = lane & 3;
    const int b = blockIdx.y;
    const int qt = (T_ / 64 - 1) - blockIdx.x;   // heavy tiles first
    const int m0 = qt * 64;
    const int rowbase = b * T_;

    // Q fragments straight from global (hi and lo), 4 k-chunks of 16.
    uint32_t qh[4][4], ql[4][4];
    {
        const size_t r0 = (size_t)(rowbase + m0 + wid * 16 + gid) * NC_;
        #pragma unroll
        for (int kc = 0; kc < 4; kc++) {
            int c0 = kc * 16 + 2 * tig;
            qh[kc][0] = *(const uint32_t*)&g_hi[r0 + c0];
            qh[kc][1] = *(const uint32_t*)&g_hi[r0 + 8 * NC_ + c0];
            qh[kc][2] = *(const uint32_t*)&g_hi[r0 + c0 + 8];
            qh[kc][3] = *(const uint32_t*)&g_hi[r0 + 8 * NC_ + c0 + 8];
            ql[kc][0] = *(const uint32_t*)&g_lo[r0 + c0];
            ql[kc][1] = *(const uint32_t*)&g_lo[r0 + 8 * NC_ + c0];
            ql[kc][2] = *(const uint32_t*)&g_lo[r0 + c0 + 8];
            ql[kc][3] = *(const uint32_t*)&g_lo[r0 + 8 * NC_ + c0 + 8];
        }
    }

    float o[8][4];
    #pragma unroll
    for (int j = 0; j < 8; j++)
        #pragma unroll
        for (int c = 0; c < 4; c++) o[j][c] = 0.0f;
    float mrow0 = -INFINITY, mrow1 = -INFINITY, lrow0 = 0.0f, lrow1 = 0.0f;

    for (int nt = 0; nt <= qt; nt++) {
        const int n0 = nt * 64;
        // Stage K,V (hi/lo) tiles into smem.
        #pragma unroll
        for (int i = 0; i < 4; i++) {
            int l2 = tid + i * 128;
            int r = l2 >> 3, cg = l2 & 7;
            const size_t g = (size_t)(rowbase + n0 + r) * NC_;
            *(uint4*)&Ks[0][r * KS_ + cg * 8] = *(const uint4*)&g_hi[g + 64 + cg * 8];
            *(uint4*)&Ks[1][r * KS_ + cg * 8] = *(const uint4*)&g_lo[g + 64 + cg * 8];
            *(uint4*)&Vs[0][r * KS_ + cg * 8] = *(const uint4*)&g_hi[g + 128 + cg * 8];
            *(uint4*)&Vs[1][r * KS_ + cg * 8] = *(const uint4*)&g_lo[g + 128 + cg * 8];
        }
        __syncthreads();

        // S = Q K^T (split-fp16, 3 mma per logical).
        float s[8][4];
        #pragma unroll
        for (int j = 0; j < 8; j++)
            #pragma unroll
            for (int c = 0; c < 4; c++) s[j][c] = 0.0f;

        #pragma unroll
        for (int kc = 0; kc < 4; kc++) {
            #pragma unroll
            for (int j = 0; j < 8; j += 2) {
                int key = 8 * j + (lane >> 4) * 8 + (lane & 7);
                int c   = kc * 16 + ((lane >> 3) & 1) * 8;
                uint32_t kh[4], kl[4];
                ldsm_x4(kh, su32(&Ks[0][key * KS_ + c]));
                ldsm_x4(kl, su32(&Ks[1][key * KS_ + c]));
                mma16816(s[j],     qh[kc], kh);
                mma16816(s[j],     qh[kc], kl);
                mma16816(s[j],     ql[kc], kh);
                mma16816(s[j + 1], qh[kc], kh + 2);
                mma16816(s[j + 1], qh[kc], kl + 2);
                mma16816(s[j + 1], ql[kc], kh + 2);
            }
        }

        // Scale + causal mask (diagonal tile only).
        const float scale = 0.125f;
        if (nt == qt) {
            int r0 = m0 + wid * 16 + gid;
            #pragma unroll
            for (int j = 0; j < 8; j++) {
                int c0 = n0 + 8 * j + 2 * tig;
                s[j][0] = (c0     <= r0)     ? s[j][0] * scale : -INFINITY;
                s[j][1] = (c0 + 1 <= r0)     ? s[j][1] * scale : -INFINITY;
                s[j][2] = (c0     <= r0 + 8) ? s[j][2] * scale : -INFINITY;
                s[j][3] = (c0 + 1 <= r0 + 8) ? s[j][3] * scale : -INFINITY;
            }
        } else {
            #pragma unroll
            for (int j = 0; j < 8; j++)
                #pragma unroll
                for (int c = 0; c < 4; c++) s[j][c] *= scale;
        }

        // Online softmax (rows gid and gid+8; reduce over 4 lanes of the group).
        float mx0 = -INFINITY, mx1 = -INFINITY;
        #pragma unroll
        for (int j = 0; j < 8; j++) {
            mx0 = fmaxf(mx0, fmaxf(s[j][0], s[j][1]));
            mx1 = fmaxf(mx1, fmaxf(s[j][2], s[j][3]));
        }
        mx0 = fmaxf(mx0, __shfl_xor_sync(0xffffffffu, mx0, 1));
        mx0 = fmaxf(mx0, __shfl_xor_sync(0xffffffffu, mx0, 2));
        mx1 = fmaxf(mx1, __shfl_xor_sync(0xffffffffu, mx1, 1));
        mx1 = fmaxf(mx1, __shfl_xor_sync(0xffffffffu, mx1, 2));
        float mn0 = fmaxf(mrow0, mx0), mn1 = fmaxf(mrow1, mx1);
        float al0 = __expf(mrow0 - mn0), al1 = __expf(mrow1 - mn1);
        float rs0 = 0.0f, rs1 = 0.0f;
        #pragma unroll
        for (int j = 0; j < 8; j++) {
            s[j][0] = __expf(s[j][0] - mn0);
            s[j][1] = __expf(s[j][1] - mn0);
            s[j][2] = __expf(s[j][2] - mn1);
            s[j][3] = __expf(s[j][3] - mn1);
            rs0 += s[j][0] + s[j][1];
            rs1 += s[j][2] + s[j][3];
        }
        rs0 += __shfl_xor_sync(0xffffffffu, rs0, 1);
        rs0 += __shfl_xor_sync(0xffffffffu, rs0, 2);
        rs1 += __shfl_xor_sync(0xffffffffu, rs1, 1);
        rs1 += __shfl_xor_sync(0xffffffffu, rs1, 2);
        lrow0 = lrow0 * al0 + rs0;
        lrow1 = lrow1 * al1 + rs1;
        mrow0 = mn0; mrow1 = mn1;
        #pragma unroll
        for (int j = 0; j < 8; j++) {
            o[j][0] *= al0; o[j][1] *= al0;
            o[j][2] *= al1; o[j][3] *= al1;
        }

        // Pack P accumulator directly into A-fragments (split hi/lo).
        uint32_t ph[4][4], pl[4][4];
        #pragma unroll
        for (int kc = 0; kc < 4; kc++) {
            int j0 = 2 * kc, j1 = 2 * kc + 1;
            split2(s[j0][0], s[j0][1], ph[kc][0], pl[kc][0]);
            split2(s[j0][2], s[j0][3], ph[kc][1], pl[kc][1]);
            split2(s[j1][0], s[j1][1], ph[kc][2], pl[kc][2]);
            split2(s[j1][2], s[j1][3], ph[kc][3], pl[kc][3]);
        }

        // O += P V (split-fp16).
        #pragma unroll
        for (int kc = 0; kc < 4; kc++) {
            #pragma unroll
            for (int j = 0; j < 8; j += 2) {
                int key  = kc * 16 + (lane & 7) + ((lane & 8) ? 8 : 0);
                int dcol = 8 * j + (lane >> 4) * 8;
                uint32_t vh[4], vl[4];
                ldsm_x4t(vh, su32(&Vs[0][key * KS_ + dcol]));
                ldsm_x4t(vl, su32(&Vs[1][key * KS_ + dcol]));
                mma16816(o[j],     ph[kc], vh);
                mma16816(o[j],     ph[kc], vl);
                mma16816(o[j],     pl[kc], vh);
                mma16816(o[j + 1], ph[kc], vh + 2);
                mma16816(o[j + 1], ph[kc], vl + 2);
                mma16816(o[j + 1], pl[kc], vh + 2);
            }
        }
        __syncthreads();
    }

    // Epilogue: normalize, store fp32.
    float inv0 = 1.0f / lrow0, inv1 = 1.0f / lrow1;
    const int r0 = m0 + wid * 16 + gid;
    float* ob = out + (size_t)b * T_ * D_;
    #pragma unroll
    for (int j = 0; j < 8; j++) {
        int c = 8 * j + 2 * tig;
        *(float2*)&ob[(size_t)r0 * D_ + c] =
            make_float2(o[j][0] * inv0, o[j][1] * inv0);
        *(float2*)&ob[(size_t)(r0 + 8) * D_ + c] =
            make_float2(o[j][2] * inv1, o[j][3] * inv1);
    }
}

// ---------------------------------------------------------------------------
extern "C" void kernel_launch(void* const* d_in, const int* in_sizes, int n_in,
                              void* d_out, int out_size)
{
    const float* x  = (const float*)d_in[0];
    const float* Wq = (const float*)d_in[1];
    const float* bq = (const float*)d_in[2];
    const float* Wk = (const float*)d_in[3];
    const float* bk = (const float*)d_in[4];
    const float* Wv = (const float*)d_in[5];
    const float* bv = (const float*)d_in[6];
    float* out = (float*)d_out;

    wprep_kernel<<<(E_ * NC_ + 255) / 256, 256>>>(Wq, Wk, Wv);
    qkv_proj_kernel<<<BT_ / 64, 256>>>(x, bq, bk, bv);
    dim3 gattn(T_ / 64, B_);
    flash_attn_kernel<<<gattn, 128>>>(out);
}